// round 2
// baseline (speedup 1.0000x reference)
#include <cuda_runtime.h>

#define B_SZ 65536
#define D_SZ 512
#define NC 16
#define V4_PER_ROW (D_SZ / 4)              // 128
#define TOTAL_V4 (B_SZ * V4_PER_ROW)       // 8,388,608
#define NBLOCKS 2048
#define NTHREADS 256
#define NPAIR (NC * (NC - 1) / 2)          // 120

__device__ float g_partials[NBLOCKS];

__global__ __launch_bounds__(NTHREADS) void k_center_partials(
    const float4* __restrict__ x,
    const int* __restrict__ y,             // int32! (JAX x64 disabled: jnp.int64 -> int32)
    const float4* __restrict__ centers)
{
    __shared__ float4 sc[NC * V4_PER_ROW];   // 32 KB
    for (int i = threadIdx.x; i < NC * V4_PER_ROW; i += NTHREADS)
        sc[i] = centers[i];
    __syncthreads();

    float acc = 0.0f;
    for (int idx = blockIdx.x * NTHREADS + threadIdx.x;
         idx < TOTAL_V4;
         idx += NBLOCKS * NTHREADS) {
        int row = idx >> 7;                  // V4_PER_ROW = 128
        int col = idx & (V4_PER_ROW - 1);
        int cls = __ldg(&y[row]) & 15;       // warp-broadcast 4B load; &15 = trap guard
        float4 xv = __ldg(&x[idx]);
        float4 cv = sc[(cls << 7) + col];
        float d0 = xv.x - cv.x;
        float d1 = xv.y - cv.y;
        float d2 = xv.z - cv.z;
        float d3 = xv.w - cv.w;
        acc = fmaf(d0, d0, acc);
        acc = fmaf(d1, d1, acc);
        acc = fmaf(d2, d2, acc);
        acc = fmaf(d3, d3, acc);
    }

    // warp reduce
    #pragma unroll
    for (int o = 16; o > 0; o >>= 1)
        acc += __shfl_down_sync(0xffffffffu, acc, o);

    __shared__ float ws[NTHREADS / 32];
    int lane = threadIdx.x & 31;
    int wid = threadIdx.x >> 5;
    if (lane == 0) ws[wid] = acc;
    __syncthreads();
    if (wid == 0) {
        float v = (lane < NTHREADS / 32) ? ws[lane] : 0.0f;
        #pragma unroll
        for (int o = 4; o > 0; o >>= 1)
            v += __shfl_down_sync(0xffffffffu, v, o);
        if (lane == 0) g_partials[blockIdx.x] = v;
    }
}

__global__ __launch_bounds__(NTHREADS) void k_finalize(
    const float4* __restrict__ centers,
    float* __restrict__ out)
{
    __shared__ float norms[NC];
    __shared__ float pairsum[NTHREADS];
    __shared__ double red[NTHREADS];
    int t = threadIdx.x;

    // class-center L2 norms
    if (t < NC) {
        float s = 0.0f;
        const float4* c = centers + t * V4_PER_ROW;
        #pragma unroll 4
        for (int i = 0; i < V4_PER_ROW; i++) {
            float4 v = c[i];
            s += v.x * v.x + v.y * v.y + v.z * v.z + v.w * v.w;
        }
        norms[t] = sqrtf(s);
    }
    __syncthreads();

    // one pair (j<k) per thread, cos + 1
    float ps = 0.0f;
    if (t < NPAIR) {
        int j = 0, rem = t;
        while (rem >= NC - 1 - j) { rem -= NC - 1 - j; j++; }
        int k = j + 1 + rem;
        const float4* cj = centers + j * V4_PER_ROW;
        const float4* ck = centers + k * V4_PER_ROW;
        float dot = 0.0f;
        #pragma unroll 4
        for (int i = 0; i < V4_PER_ROW; i++) {
            float4 a = cj[i];
            float4 b = ck[i];
            dot += a.x * b.x + a.y * b.y + a.z * b.z + a.w * b.w;
        }
        float denom = norms[j] * norms[k] + 1e-9f;
        ps = dot / denom + 1.0f;
    }
    pairsum[t] = ps;

    // strided partial-sum accumulation (deterministic fixed order)
    double s = 0.0;
    for (int i = t; i < NBLOCKS; i += NTHREADS)
        s += (double)g_partials[i];
    red[t] = s;
    __syncthreads();

    // fixed-order tree reduce for both sums
    for (int stride = NTHREADS / 2; stride > 0; stride >>= 1) {
        if (t < stride) {
            red[t] += red[t + stride];
            pairsum[t] += pairsum[t + stride];
        }
        __syncthreads();
    }

    if (t == 0) {
        // SCALE = 1, LAMDA = 1, LAMDA1 = 10
        float loss_center = 0.5f * (float)red[0] * (1.0f / (float)B_SZ);
        out[0] = loss_center + 10.0f * pairsum[0];
    }
}

extern "C" void kernel_launch(void* const* d_in, const int* in_sizes, int n_in,
                              void* d_out, int out_size)
{
    // Identify inputs by element count (robust to ordering):
    //   output_features: 65536*512 = 33554432
    //   y_truth:         65536
    //   feature_centers: 16*512   = 8192
    const float4* x = nullptr;
    const int* y = nullptr;
    const float4* centers = nullptr;
    for (int i = 0; i < n_in; i++) {
        if (in_sizes[i] == 33554432)      x = (const float4*)d_in[i];
        else if (in_sizes[i] == 65536)    y = (const int*)d_in[i];
        else if (in_sizes[i] == 8192)     centers = (const float4*)d_in[i];
    }
    float* out = (float*)d_out;

    k_center_partials<<<NBLOCKS, NTHREADS>>>(x, y, centers);
    k_finalize<<<1, NTHREADS>>>(centers, out);
}

// round 3
// speedup vs baseline: 1.5126x; 1.5126x over previous
#include <cuda_runtime.h>

#define B_SZ 65536
#define D_SZ 512
#define NC 16
#define V4_PER_ROW (D_SZ / 4)              // 128
#define NBLOCKS 2048
#define NTHREADS 256
#define WARPS_PER_BLOCK (NTHREADS / 32)    // 8
#define ROWS_PER_WARP 4                    // 65536 / (2048*8)
#define NPAIR (NC * (NC - 1) / 2)          // 120
#define PAIRS_PER_WARP (NPAIR / WARPS_PER_BLOCK)  // 15

__device__ float g_partials[NBLOCKS];

__global__ __launch_bounds__(NTHREADS) void k_center_partials(
    const float4* __restrict__ x,
    const int* __restrict__ y,             // int32 (JAX x64 disabled)
    const float4* __restrict__ centers)
{
    __shared__ float4 sc[NC * V4_PER_ROW];   // 32 KB
    #pragma unroll
    for (int i = 0; i < (NC * V4_PER_ROW) / NTHREADS; i++)
        sc[i * NTHREADS + threadIdx.x] = centers[i * NTHREADS + threadIdx.x];
    __syncthreads();

    const int lane = threadIdx.x & 31;
    const int gw = blockIdx.x * WARPS_PER_BLOCK + (threadIdx.x >> 5);

    float acc = 0.0f;
    #pragma unroll
    for (int r = 0; r < ROWS_PER_WARP; r++) {
        const int row = gw * ROWS_PER_WARP + r;
        const int cls = __ldg(&y[row]) & 15;          // broadcast load
        const float4* __restrict__ xr = x + (size_t)row * V4_PER_ROW;
        const float4* __restrict__ cr = sc + (cls << 7);
        #pragma unroll
        for (int i = 0; i < 4; i++) {
            float4 xv = __ldg(&xr[i * 32 + lane]);    // coalesced 512B
            float4 cv = cr[i * 32 + lane];            // conflict-free LDS.128
            float d0 = xv.x - cv.x;
            float d1 = xv.y - cv.y;
            float d2 = xv.z - cv.z;
            float d3 = xv.w - cv.w;
            acc = fmaf(d0, d0, acc);
            acc = fmaf(d1, d1, acc);
            acc = fmaf(d2, d2, acc);
            acc = fmaf(d3, d3, acc);
        }
    }

    // warp reduce
    #pragma unroll
    for (int o = 16; o > 0; o >>= 1)
        acc += __shfl_down_sync(0xffffffffu, acc, o);

    __shared__ float ws[WARPS_PER_BLOCK];
    const int wid = threadIdx.x >> 5;
    if (lane == 0) ws[wid] = acc;
    __syncthreads();
    if (wid == 0) {
        float v = (lane < WARPS_PER_BLOCK) ? ws[lane] : 0.0f;
        #pragma unroll
        for (int o = 4; o > 0; o >>= 1)
            v += __shfl_down_sync(0xffffffffu, v, o);
        if (lane == 0) g_partials[blockIdx.x] = v;
    }
}

__global__ __launch_bounds__(NTHREADS) void k_finalize(
    const float4* __restrict__ centers,
    float* __restrict__ out)
{
    __shared__ float4 sc[NC * V4_PER_ROW];   // 32 KB
    __shared__ float norms[NC];
    __shared__ float warp_pair[WARPS_PER_BLOCK];
    __shared__ double red[NTHREADS];

    const int t = threadIdx.x;
    const int lane = t & 31;
    const int wid = t >> 5;

    // Stage centers (coalesced, MLP=8)
    #pragma unroll
    for (int i = 0; i < (NC * V4_PER_ROW) / NTHREADS; i++)
        sc[i * NTHREADS + t] = centers[i * NTHREADS + t];

    // Start partials sum in parallel with the smem staging latency
    double s = 0.0;
    #pragma unroll
    for (int i = 0; i < NBLOCKS / NTHREADS; i++)
        s += (double)g_partials[i * NTHREADS + t];
    red[t] = s;
    __syncthreads();

    // Norms: warp-per-row, 2 rows per warp (8 warps x 2 = 16)
    #pragma unroll
    for (int r = 0; r < 2; r++) {
        const int row = wid * 2 + r;
        const float4* cr = sc + (row << 7);
        float ns = 0.0f;
        #pragma unroll
        for (int i = 0; i < 4; i++) {
            float4 v = cr[i * 32 + lane];
            ns += v.x * v.x + v.y * v.y + v.z * v.z + v.w * v.w;
        }
        #pragma unroll
        for (int o = 16; o > 0; o >>= 1)
            ns += __shfl_down_sync(0xffffffffu, ns, o);
        if (lane == 0) norms[row] = sqrtf(ns);
    }
    __syncthreads();

    // Pairs: warp-per-pair, 15 pairs per warp, fixed order per warp
    float psum = 0.0f;
    #pragma unroll
    for (int pp = 0; pp < PAIRS_PER_WARP; pp++) {
        const int p = wid * PAIRS_PER_WARP + pp;
        // decode (j,k) from linear upper-triangle index
        int j = 0, rem = p;
        while (rem >= NC - 1 - j) { rem -= NC - 1 - j; j++; }
        const int k = j + 1 + rem;
        const float4* cj = sc + (j << 7);
        const float4* ck = sc + (k << 7);
        float dot = 0.0f;
        #pragma unroll
        for (int i = 0; i < 4; i++) {
            float4 a = cj[i * 32 + lane];
            float4 b = ck[i * 32 + lane];
            dot += a.x * b.x + a.y * b.y + a.z * b.z + a.w * b.w;
        }
        #pragma unroll
        for (int o = 16; o > 0; o >>= 1)
            dot += __shfl_down_sync(0xffffffffu, dot, o);
        if (lane == 0)
            psum += dot / (norms[j] * norms[k] + 1e-9f) + 1.0f;
    }
    if (lane == 0) warp_pair[wid] = psum;
    __syncthreads();

    // Fixed-order tree reduce of the double partials
    for (int stride = NTHREADS / 2; stride > 0; stride >>= 1) {
        if (t < stride) red[t] += red[t + stride];
        __syncthreads();
    }

    if (t == 0) {
        float island = 0.0f;
        #pragma unroll
        for (int w = 0; w < WARPS_PER_BLOCK; w++)
            island += warp_pair[w];
        // SCALE = 1, LAMDA = 1, LAMDA1 = 10
        float loss_center = 0.5f * (float)red[0] * (1.0f / (float)B_SZ);
        out[0] = loss_center + 10.0f * island;
    }
}

extern "C" void kernel_launch(void* const* d_in, const int* in_sizes, int n_in,
                              void* d_out, int out_size)
{
    // Identify inputs by element count (robust to ordering):
    //   output_features: 65536*512 = 33554432
    //   y_truth:         65536
    //   feature_centers: 16*512   = 8192
    const float4* x = nullptr;
    const int* y = nullptr;
    const float4* centers = nullptr;
    for (int i = 0; i < n_in; i++) {
        if (in_sizes[i] == 33554432)      x = (const float4*)d_in[i];
        else if (in_sizes[i] == 65536)    y = (const int*)d_in[i];
        else if (in_sizes[i] == 8192)     centers = (const float4*)d_in[i];
    }
    float* out = (float*)d_out;

    k_center_partials<<<NBLOCKS, NTHREADS>>>(x, y, centers);
    k_finalize<<<1, NTHREADS>>>(centers, out);
}

// round 4
// speedup vs baseline: 1.5218x; 1.0061x over previous
#include <cuda_runtime.h>

#define B_SZ 65536
#define D_SZ 512
#define NC 16
#define V4_PER_ROW (D_SZ / 4)              // 128
#define NBLOCKS 1024                       // single fully-resident wave (7 CTA/SM x 148 > 1024)
#define NTHREADS 256
#define WARPS_PER_BLOCK (NTHREADS / 32)    // 8
#define ROWS_PER_WARP 8                    // 1024*8*8 = 65536
#define NPAIR (NC * (NC - 1) / 2)          // 120
#define PAIRS_PER_WARP (NPAIR / WARPS_PER_BLOCK)  // 15

__device__ float g_partials[NBLOCKS];
__device__ unsigned int g_ticket = 0;      // wraps back to 0 every NBLOCKS atomicInc's

__global__ __launch_bounds__(NTHREADS) void k_island_fused(
    const float4* __restrict__ x,
    const int* __restrict__ y,             // int32 (JAX x64 disabled)
    const float4* __restrict__ centers,
    float* __restrict__ out)
{
    __shared__ float4 sc[NC * V4_PER_ROW];   // 32 KB, centers (kept hot for last block too)
    __shared__ float ws[WARPS_PER_BLOCK];
    __shared__ unsigned int s_ticket;

    const int t = threadIdx.x;
    const int lane = t & 31;
    const int wid = t >> 5;

    #pragma unroll
    for (int i = 0; i < (NC * V4_PER_ROW) / NTHREADS; i++)
        sc[i * NTHREADS + t] = centers[i * NTHREADS + t];
    __syncthreads();

    // ---- Phase 1: streaming center-loss partial ----
    const int gw = blockIdx.x * WARPS_PER_BLOCK + wid;
    const int rowbase = gw * ROWS_PER_WARP;

    // one coalesced load of the 8 row labels, broadcast via shfl
    int myy = (lane < ROWS_PER_WARP) ? __ldg(&y[rowbase + lane]) : 0;

    float a0 = 0.f, a1 = 0.f, a2 = 0.f, a3 = 0.f;
    #pragma unroll
    for (int r = 0; r < ROWS_PER_WARP; r++) {
        const int cls = __shfl_sync(0xffffffffu, myy, r) & 15;
        const float4* __restrict__ xr = x + (size_t)(rowbase + r) * V4_PER_ROW;
        const float4* __restrict__ cr = sc + (cls << 7);
        #pragma unroll
        for (int i = 0; i < 4; i++) {
            float4 xv = __ldg(&xr[i * 32 + lane]);    // coalesced 512B / instr
            float4 cv = cr[i * 32 + lane];            // conflict-free LDS.128
            float d0 = xv.x - cv.x;
            float d1 = xv.y - cv.y;
            float d2 = xv.z - cv.z;
            float d3 = xv.w - cv.w;
            a0 = fmaf(d0, d0, a0);
            a1 = fmaf(d1, d1, a1);
            a2 = fmaf(d2, d2, a2);
            a3 = fmaf(d3, d3, a3);
        }
    }
    float acc = (a0 + a1) + (a2 + a3);

    #pragma unroll
    for (int o = 16; o > 0; o >>= 1)
        acc += __shfl_down_sync(0xffffffffu, acc, o);
    if (lane == 0) ws[wid] = acc;
    __syncthreads();
    if (t == 0) {
        float v = 0.f;
        #pragma unroll
        for (int w = 0; w < WARPS_PER_BLOCK; w++) v += ws[w];
        g_partials[blockIdx.x] = v;
        __threadfence();
        // wrapping ticket: after NBLOCKS increments it returns to 0 (graph-replay safe)
        s_ticket = atomicInc(&g_ticket, NBLOCKS - 1);
    }
    __syncthreads();
    if (s_ticket != NBLOCKS - 1)
        return;                                       // not the last block

    // ---- Phase 2 (last block only): island term + final reduce ----
    __shared__ float norms[NC];
    __shared__ float warp_pair[WARPS_PER_BLOCK];
    __shared__ double red[NTHREADS];

    // partials: 1024 floats, L2-hot, fixed order
    double s = 0.0;
    #pragma unroll
    for (int i = 0; i < NBLOCKS / NTHREADS; i++)
        s += (double)g_partials[i * NTHREADS + t];
    red[t] = s;

    // norms: warp-per-2-rows (centers still in sc)
    #pragma unroll
    for (int r = 0; r < 2; r++) {
        const int row = wid * 2 + r;
        const float4* cr = sc + (row << 7);
        float ns = 0.0f;
        #pragma unroll
        for (int i = 0; i < 4; i++) {
            float4 v = cr[i * 32 + lane];
            ns += v.x * v.x + v.y * v.y + v.z * v.z + v.w * v.w;
        }
        #pragma unroll
        for (int o = 16; o > 0; o >>= 1)
            ns += __shfl_down_sync(0xffffffffu, ns, o);
        if (lane == 0) norms[row] = sqrtf(ns);
    }
    __syncthreads();

    // pairs: 15 per warp, fixed order
    float psum = 0.0f;
    #pragma unroll
    for (int pp = 0; pp < PAIRS_PER_WARP; pp++) {
        const int p = wid * PAIRS_PER_WARP + pp;
        int j = 0, rem = p;
        while (rem >= NC - 1 - j) { rem -= NC - 1 - j; j++; }
        const int k = j + 1 + rem;
        const float4* cj = sc + (j << 7);
        const float4* ck = sc + (k << 7);
        float dot = 0.0f;
        #pragma unroll
        for (int i = 0; i < 4; i++) {
            float4 a = cj[i * 32 + lane];
            float4 b = ck[i * 32 + lane];
            dot += a.x * b.x + a.y * b.y + a.z * b.z + a.w * b.w;
        }
        #pragma unroll
        for (int o = 16; o > 0; o >>= 1)
            dot += __shfl_down_sync(0xffffffffu, dot, o);
        if (lane == 0)
            psum += dot / (norms[j] * norms[k] + 1e-9f) + 1.0f;
    }
    if (lane == 0) warp_pair[wid] = psum;
    __syncthreads();

    // fixed-order tree reduce of double partials
    for (int stride = NTHREADS / 2; stride > 0; stride >>= 1) {
        if (t < stride) red[t] += red[t + stride];
        __syncthreads();
    }

    if (t == 0) {
        float island = 0.0f;
        #pragma unroll
        for (int w = 0; w < WARPS_PER_BLOCK; w++)
            island += warp_pair[w];
        // SCALE = 1, LAMDA = 1, LAMDA1 = 10
        float loss_center = 0.5f * (float)red[0] * (1.0f / (float)B_SZ);
        out[0] = loss_center + 10.0f * island;
    }
}

extern "C" void kernel_launch(void* const* d_in, const int* in_sizes, int n_in,
                              void* d_out, int out_size)
{
    // Identify inputs by element count (robust to ordering):
    //   output_features: 65536*512 = 33554432
    //   y_truth:         65536
    //   feature_centers: 16*512   = 8192
    const float4* x = nullptr;
    const int* y = nullptr;
    const float4* centers = nullptr;
    for (int i = 0; i < n_in; i++) {
        if (in_sizes[i] == 33554432)      x = (const float4*)d_in[i];
        else if (in_sizes[i] == 65536)    y = (const int*)d_in[i];
        else if (in_sizes[i] == 8192)     centers = (const float4*)d_in[i];
    }
    float* out = (float*)d_out;

    k_island_fused<<<NBLOCKS, NTHREADS>>>(x, y, centers, out);
}